// round 9
// baseline (speedup 1.0000x reference)
#include <cuda_runtime.h>

#define BATCH 1024
#define RC 64
#define NL 24
#define QL 128
#define TB 8                     // batch rows per compute block
#define NCOMP (BATCH / TB)       // 128 compute blocks
#define CTHREADS 1024            // 4 groups of 256; each thread: 2 rows
#define NTHREADS 256
#define NQ ((size_t)NL * BATCH * RC * QL)   // 201326592 queue elements
#define NROWS (NQ / 128)                    // 1572864 rows of 128 floats
#define RPW 64                              // rows per copy warp
#define WARPS_PER_BLK 8
#define NCOPY ((int)(NROWS / (RPW * WARPS_PER_BLK)))   // 3072 copy blocks
#define LSTR ((size_t)BATCH * RC)           // row index stride per layer
#define NWT (NL * RC * 256)                 // transposed weight elements
#define SMEM_BYTES ((NL*TB*RC + TB*RC + TB*RC + TB*4*RC) * 4)  // 61440

// Transposed weights: lane-coalesced for thread==j mapping.
__device__ float2 g_convT[NWT];             // [i][rc][j] -> (w0, w1)
__device__ float  g_fc1T[NWT];              // [i][rc][j]

__device__ __forceinline__ float sigf(float x) { return 1.0f / (1.0f + __expf(-x)); }

// ---------------------------------------------------------------------------
// WEIGHT TRANSPOSE: conv_w [i][j][rc][2] -> convT [i][rc][j] float2
//                   fc1_w  [j][i*64+rc]  -> fc1T  [i][rc][j]
// ---------------------------------------------------------------------------
__global__ void __launch_bounds__(NTHREADS)
transpose_weights_kernel(const float* __restrict__ conv_w,
                         const float* __restrict__ fc1_w)
{
    int idx = blockIdx.x * NTHREADS + threadIdx.x;   // ((i*64+rc)*256+j)
    if (idx >= NWT) return;
    int j    = idx & 255;
    int rcil = idx >> 8;
    int rc   = rcil & 63;
    int i    = rcil >> 6;
    const float* cw = conv_w + (((size_t)i * 256 + j) * 64 + rc) * 2;
    g_convT[idx] = make_float2(cw[0], cw[1]);
    g_fc1T[idx]  = fc1_w[(size_t)j * (NL * RC) + i * 64 + rc];
}

// Store one 128-float row (held as float4 v per lane) to dstq + R*129,
// realigned so the bulk goes out as one aligned STG.128 per lane.
__device__ __forceinline__ void store_row(float* __restrict__ dstq, size_t R,
                                          int lane, float4 v)
{
    float* base = dstq + R * 129;
    unsigned m = (unsigned)(R & 3);          // base misalignment in floats
    if (m == 0) {
        *(float4*)(base + 4 * lane) = v;
        return;
    }
    unsigned s = 4 - m;                      // shift: first aligned float index
    float nx = __shfl_down_sync(0xffffffffu, v.x, 1);
    float ny = __shfl_down_sync(0xffffffffu, v.y, 1);
    float nz = __shfl_down_sync(0xffffffffu, v.z, 1);
    float4 w;
    if (s == 1)      w = make_float4(v.y, v.z, v.w, nx);
    else if (s == 2) w = make_float4(v.z, v.w, nx, ny);
    else             w = make_float4(v.w, nx, ny, nz);
    if (lane < 31)
        *(float4*)(base + s + 4 * lane) = w; // 16B-aligned bulk
    if (lane == 0) {                         // head floats j = 0..s-1
        base[0] = v.x;
        if (s >= 2) base[1] = v.y;
        if (s >= 3) base[2] = v.z;
    }
    if (lane == 31) {                        // tail floats j = s+124..127
        base[127] = v.w;
        if (s <= 2) base[126] = v.z;
        if (s <= 1) base[125] = v.y;
    }
}

// ---------------------------------------------------------------------------
// COPY KERNEL: queues (.., 128) -> out queue region (.., 129), t < 128.
// (Proven: 313us standalone, 5.1 TB/s, occ 88%.)
// ---------------------------------------------------------------------------
__global__ void __launch_bounds__(NTHREADS)
queue_copy_kernel(const float* __restrict__ queues, float* __restrict__ out)
{
    const float4* __restrict__ src = (const float4*)queues;
    float* __restrict__ dstq = out + BATCH;
    const int lane = threadIdx.x & 31;
    size_t R = ((size_t)blockIdx.x * WARPS_PER_BLK + (threadIdx.x >> 5)) * RPW;

    #pragma unroll 1
    for (int it = 0; it < RPW / 4; it++, R += 4) {
        float4 v0 = __ldcs(&src[(R)     * 32 + lane]);
        float4 v1 = __ldcs(&src[(R + 1) * 32 + lane]);
        float4 v2 = __ldcs(&src[(R + 2) * 32 + lane]);
        float4 v3 = __ldcs(&src[(R + 3) * 32 + lane]);
        store_row(dstq, R,     lane, v0);
        store_row(dstq, R + 1, lane, v1);
        store_row(dstq, R + 2, lane, v2);
        store_row(dstq, R + 3, lane, v3);
    }
}

// ---------------------------------------------------------------------------
// COMPUTE KERNEL: 1024 threads, TB=8 rows. Group g = tid>>8 handles rows
// {2g, 2g+1} with channel j = tid&255. fc1 of layer i-1 is fused into the
// conv loop of layer i (same s_h reads). 128 blocks halve L2 weight traffic.
// ---------------------------------------------------------------------------
__global__ void __launch_bounds__(CTHREADS, 1)
wave_compute_kernel(const float* __restrict__ x,
                    const float* __restrict__ features,
                    const float* __restrict__ queues,
                    const float* __restrict__ fc_h_w,
                    const float* __restrict__ fc_h_b,
                    const float* __restrict__ fc_c_w,
                    const float* __restrict__ fc_c_b,
                    const float* __restrict__ conv_b,
                    const float* __restrict__ fc1_b,
                    const float* __restrict__ fc2_w,
                    const float* __restrict__ fc2_b,
                    float* __restrict__ out)
{
    extern __shared__ __align__(16) float smem[];
    float (*s_pv)[TB][RC] = (float (*)[TB][RC])smem;             // 48 KB
    float (*s_h)[RC]  = (float (*)[RC])(smem + NL * TB * RC);    // 2 KB
    float (*s_c)[RC]  = (float (*)[RC])(smem + NL * TB * RC + TB * RC);
    float (*s_co)[4 * RC] =
        (float (*)[4 * RC])(smem + NL * TB * RC + 2 * TB * RC);  // 8 KB

    const int tid = threadIdx.x;
    const int b0  = blockIdx.x * TB;
    const int g   = tid >> 8;          // 0..3: handles rows t0, t0+1
    const int j   = tid & 255;
    const int t0  = g * 2;

    // ---- prefetch ALL 24 layers' dilated queue values into shared ----
    for (int idx = tid; idx < NL * TB * RC; idx += CTHREADS) {
        int i = idx >> 9;              // / (TB*RC)
        int t = (idx >> 6) & 7;
        int r = idx & 63;
        s_pv[i][t][r] = __ldg(queues
            + (((size_t)(b0 + t) * RC + r) + (size_t)i * LSTR) * QL
            + QL - (1 << (i & 7)));
    }

    // ---- initial h, c = tanh(inp @ W^T + b)  (threads 0..511) ----
    float* __restrict__ outq = out + BATCH;
    size_t ebase = 0;
    if (tid < TB * RC) {
        int t = tid >> 6, r = tid & 63;
        int b = b0 + t;
        ebase = (size_t)b * RC + r;
        const float* wh = fc_h_w + r * 33;
        const float* wc = fc_c_w + r * 33;
        float ah = fc_h_b[r], ac = fc_c_b[r];
        float xv = x[b];
        ah += xv * wh[0];
        ac += xv * wc[0];
        const float* fb = features + b * 32;
        #pragma unroll
        for (int k = 0; k < 32; k++) {
            float f = fb[k];
            ah += f * wh[1 + k];
            ac += f * wc[1 + k];
        }
        float h0 = tanhf(ah);
        s_h[t][r] = h0;
        s_c[t][r] = tanhf(ac);
        outq[ebase * 129 + QL] = h0;           // entry for layer 0
    }

    float yacc0 = fc1_b[j], yacc1 = yacc0;
    __syncthreads();

    const float2* __restrict__ wcv = g_convT + j;   // + (i*64+rc)*256
    const float*  __restrict__ wf1 = g_fc1T  + j;

    for (int i = 0; i < NL; i++) {
        // ---- conv layer i (+ fused fc1 of layer i-1, reading same s_h) ----
        float acc0, acc1;
        acc0 = acc1 = __ldg(conv_b + i * 256 + j);
        const float2* wci = wcv + (size_t)i * (RC * 256);
        const float*  f1p = wf1 + (size_t)(i - 1) * (RC * 256);
        const bool addf = (i > 0);
        #pragma unroll 4
        for (int rc = 0; rc < RC; rc += 4) {
            float2 w0 = __ldg(&wci[(rc + 0) << 8]);
            float2 w1 = __ldg(&wci[(rc + 1) << 8]);
            float2 w2 = __ldg(&wci[(rc + 2) << 8]);
            float2 w3 = __ldg(&wci[(rc + 3) << 8]);
            float a0 = 0.f, a1 = 0.f, a2 = 0.f, a3 = 0.f;
            if (addf) {
                a0 = __ldg(&f1p[(rc + 0) << 8]);
                a1 = __ldg(&f1p[(rc + 1) << 8]);
                a2 = __ldg(&f1p[(rc + 2) << 8]);
                a3 = __ldg(&f1p[(rc + 3) << 8]);
            }
            {
                float4 p  = *(const float4*)&s_pv[i][t0][rc];
                float4 hh = *(const float4*)&s_h[t0][rc];
                acc0 += p.x * w0.x + hh.x * w0.y;
                acc0 += p.y * w1.x + hh.y * w1.y;
                acc0 += p.z * w2.x + hh.z * w2.y;
                acc0 += p.w * w3.x + hh.w * w3.y;
                yacc0 += hh.x * a0 + hh.y * a1 + hh.z * a2 + hh.w * a3;
            }
            {
                float4 p  = *(const float4*)&s_pv[i][t0 + 1][rc];
                float4 hh = *(const float4*)&s_h[t0 + 1][rc];
                acc1 += p.x * w0.x + hh.x * w0.y;
                acc1 += p.y * w1.x + hh.y * w1.y;
                acc1 += p.z * w2.x + hh.z * w2.y;
                acc1 += p.w * w3.x + hh.w * w3.y;
                yacc1 += hh.x * a0 + hh.y * a1 + hh.z * a2 + hh.w * a3;
            }
        }
        s_co[t0][j]     = acc0;
        s_co[t0 + 1][j] = acc1;
        __syncthreads();

        // ---- gate update (threads 0..511); write next layer's entry ----
        if (tid < TB * RC) {
            int t = tid >> 6, r = tid & 63;
            float ig = s_co[t][r];
            float cf = s_co[t][RC + r];
            float cg = s_co[t][2 * RC + r];
            float eg = s_co[t][3 * RC + r];
            float c = sigf(ig) * s_c[t][r] + tanhf(cf) * sigf(cg);
            float h = sigf(eg) * tanhf(c);
            s_c[t][r] = c;
            s_h[t][r] = h;
            if (i + 1 < NL)                    // entry_h for layer i+1
                outq[(ebase + (size_t)(i + 1) * LSTR) * 129 + QL] = h;
        }
        __syncthreads();
    }

    // ---- trailing fc1 for layer 23's skip-h ----
    {
        const float* f1p = wf1 + (size_t)(NL - 1) * (RC * 256);
        #pragma unroll 4
        for (int rc = 0; rc < RC; rc += 4) {
            float a0 = __ldg(&f1p[(rc + 0) << 8]);
            float a1 = __ldg(&f1p[(rc + 1) << 8]);
            float a2 = __ldg(&f1p[(rc + 2) << 8]);
            float a3 = __ldg(&f1p[(rc + 3) << 8]);
            {
                float4 hh = *(const float4*)&s_h[t0][rc];
                yacc0 += hh.x * a0 + hh.y * a1 + hh.z * a2 + hh.w * a3;
            }
            {
                float4 hh = *(const float4*)&s_h[t0 + 1][rc];
                yacc1 += hh.x * a0 + hh.y * a1 + hh.z * a2 + hh.w * a3;
            }
        }
    }

    // ---- fc2: h_hat[b] = relu(y) @ fc2_w^T + fc2_b ----
    __syncthreads();
    {
        float fw = fc2_w[j];
        s_co[t0][j]     = fmaxf(yacc0, 0.0f) * fw;
        s_co[t0 + 1][j] = fmaxf(yacc1, 0.0f) * fw;
    }
    __syncthreads();

    int w = tid >> 5, lane = tid & 31;
    if (w < TB) {                        // warps 0..7 reduce the TB rows
        float s = 0.0f;
        #pragma unroll
        for (int k = 0; k < 8; k++) s += s_co[w][lane + k * 32];
        #pragma unroll
        for (int o = 16; o > 0; o >>= 1) s += __shfl_xor_sync(0xffffffffu, s, o);
        if (lane == 0) out[b0 + w] = s + fc2_b[0];
    }
}

extern "C" void kernel_launch(void* const* d_in, const int* in_sizes, int n_in,
                              void* d_out, int out_size)
{
    const float* x        = (const float*)d_in[0];
    const float* features = (const float*)d_in[1];
    const float* queues   = (const float*)d_in[2];
    const float* fc_h_w   = (const float*)d_in[3];
    const float* fc_h_b   = (const float*)d_in[4];
    const float* fc_c_w   = (const float*)d_in[5];
    const float* fc_c_b   = (const float*)d_in[6];
    const float* conv_w   = (const float*)d_in[7];
    const float* conv_b   = (const float*)d_in[8];
    const float* fc1_w    = (const float*)d_in[9];
    const float* fc1_b    = (const float*)d_in[10];
    const float* fc2_w    = (const float*)d_in[11];
    const float* fc2_b    = (const float*)d_in[12];
    float* out = (float*)d_out;

    static int smem_set = 0;
    if (!smem_set) {
        cudaFuncSetAttribute(wave_compute_kernel,
                             cudaFuncAttributeMaxDynamicSharedMemorySize,
                             SMEM_BYTES);
        smem_set = 1;
    }

    // Serial: transpose (tiny) -> compute (weights warm in L2) -> copy.
    transpose_weights_kernel<<<(NWT + NTHREADS - 1) / NTHREADS, NTHREADS>>>(
        conv_w, fc1_w);

    wave_compute_kernel<<<NCOMP, CTHREADS, SMEM_BYTES>>>(
        x, features, queues, fc_h_w, fc_h_b, fc_c_w, fc_c_b,
        conv_b, fc1_b, fc2_w, fc2_b, out);

    queue_copy_kernel<<<NCOPY, NTHREADS>>>(queues, out);
}

// round 10
// speedup vs baseline: 1.0012x; 1.0012x over previous
#include <cuda_runtime.h>

#define BATCH 1024
#define RC 64
#define NL 24
#define QL 128
#define TB 4                     // batch rows per compute block
#define NCOMP (BATCH / TB)       // 256 compute blocks
#define CTHREADS 512             // 2 groups of 256; each thread: 2 rows
#define NTHREADS 256
#define NQ ((size_t)NL * BATCH * RC * QL)   // 201326592 queue elements
#define NROWS (NQ / 128)                    // 1572864 rows of 128 floats
#define RPW 64                              // rows per copy warp
#define WARPS_PER_BLK 8
#define NCOPY ((int)(NROWS / (RPW * WARPS_PER_BLK)))   // 3072 copy blocks
#define LSTR ((size_t)BATCH * RC)           // row index stride per layer
#define NCONVP (NL * 32 * 256)              // packed conv float4 count
#define NFC1P  (NL * 16 * 256)              // packed fc1 float4 count

// Packed transposed weights, lane-coalesced for thread==j mapping.
__device__ float4 g_convP[NCONVP];   // [i][p][j] = (w0[2p],w1[2p],w0[2p+1],w1[2p+1])
__device__ float4 g_fc1P[NFC1P];     // [i][q][j] = fc1[rc=4q..4q+3]

__device__ __forceinline__ float sigf(float x) { return 1.0f / (1.0f + __expf(-x)); }

// ---------------------------------------------------------------------------
// WEIGHT TRANSPOSE (packed float4):
//   conv_w row (i,j) is 128 contiguous floats [rc][2]; float4 #p of that row
//   is exactly (w0[2p],w1[2p],w0[2p+1],w1[2p+1]).
//   fc1_w row j is 1536 contiguous floats; float4 #(i*16+q) is fc1[i][4q..4q+3].
// ---------------------------------------------------------------------------
__global__ void __launch_bounds__(NTHREADS)
transpose_weights_kernel(const float* __restrict__ conv_w,
                         const float* __restrict__ fc1_w)
{
    int idx = blockIdx.x * NTHREADS + threadIdx.x;   // ((i*32+p)*256+j)
    if (idx < NCONVP) {
        int j  = idx & 255;
        int pi = idx >> 8;           // i*32 + p
        int p  = pi & 31;
        int i  = pi >> 5;
        g_convP[idx] =
            __ldg((const float4*)(conv_w + (((size_t)i * 256 + j) << 7)) + p);
    }
    if (idx < NFC1P) {
        int j  = idx & 255;
        int qi = idx >> 8;           // i*16 + q
        g_fc1P[idx] =
            __ldg((const float4*)(fc1_w + (size_t)j * (NL * RC)) + qi);
    }
}

// Store one 128-float row (held as float4 v per lane) to dstq + R*129,
// realigned so the bulk goes out as one aligned STG.128 per lane.
__device__ __forceinline__ void store_row(float* __restrict__ dstq, size_t R,
                                          int lane, float4 v)
{
    float* base = dstq + R * 129;
    unsigned m = (unsigned)(R & 3);          // base misalignment in floats
    if (m == 0) {
        *(float4*)(base + 4 * lane) = v;
        return;
    }
    unsigned s = 4 - m;                      // shift: first aligned float index
    float nx = __shfl_down_sync(0xffffffffu, v.x, 1);
    float ny = __shfl_down_sync(0xffffffffu, v.y, 1);
    float nz = __shfl_down_sync(0xffffffffu, v.z, 1);
    float4 w;
    if (s == 1)      w = make_float4(v.y, v.z, v.w, nx);
    else if (s == 2) w = make_float4(v.z, v.w, nx, ny);
    else             w = make_float4(v.w, nx, ny, nz);
    if (lane < 31)
        *(float4*)(base + s + 4 * lane) = w; // 16B-aligned bulk
    if (lane == 0) {                         // head floats j = 0..s-1
        base[0] = v.x;
        if (s >= 2) base[1] = v.y;
        if (s >= 3) base[2] = v.z;
    }
    if (lane == 31) {                        // tail floats j = s+124..127
        base[127] = v.w;
        if (s <= 2) base[126] = v.z;
        if (s <= 1) base[125] = v.y;
    }
}

// ---------------------------------------------------------------------------
// COPY KERNEL: queues (.., 128) -> out queue region (.., 129), t < 128.
// (Proven: 313us standalone, 5.1 TB/s, occ 88%.)
// ---------------------------------------------------------------------------
__global__ void __launch_bounds__(NTHREADS)
queue_copy_kernel(const float* __restrict__ queues, float* __restrict__ out)
{
    const float4* __restrict__ src = (const float4*)queues;
    float* __restrict__ dstq = out + BATCH;
    const int lane = threadIdx.x & 31;
    size_t R = ((size_t)blockIdx.x * WARPS_PER_BLK + (threadIdx.x >> 5)) * RPW;

    #pragma unroll 1
    for (int it = 0; it < RPW / 4; it++, R += 4) {
        float4 v0 = __ldcs(&src[(R)     * 32 + lane]);
        float4 v1 = __ldcs(&src[(R + 1) * 32 + lane]);
        float4 v2 = __ldcs(&src[(R + 2) * 32 + lane]);
        float4 v3 = __ldcs(&src[(R + 3) * 32 + lane]);
        store_row(dstq, R,     lane, v0);
        store_row(dstq, R + 1, lane, v1);
        store_row(dstq, R + 2, lane, v2);
        store_row(dstq, R + 3, lane, v3);
    }
}

// ---------------------------------------------------------------------------
// COMPUTE KERNEL: 512 threads, TB=4 rows (R8 shape). Group g = tid>>8
// handles rows {2g, 2g+1} with channel j = tid&255. fc1 of layer i-1 is
// fused into layer i's conv loop. Weights read as packed float4 (3 LDG.128
// per 4-rc block instead of 8 loads).
// ---------------------------------------------------------------------------
__global__ void __launch_bounds__(CTHREADS, 2)
wave_compute_kernel(const float* __restrict__ x,
                    const float* __restrict__ features,
                    const float* __restrict__ queues,
                    const float* __restrict__ fc_h_w,
                    const float* __restrict__ fc_h_b,
                    const float* __restrict__ fc_c_w,
                    const float* __restrict__ fc_c_b,
                    const float* __restrict__ conv_b,
                    const float* __restrict__ fc1_b,
                    const float* __restrict__ fc2_w,
                    const float* __restrict__ fc2_b,
                    float* __restrict__ out)
{
    __shared__ __align__(16) float s_h[TB][RC];
    __shared__ __align__(16) float s_c[TB][RC];
    __shared__ __align__(16) float s_pv[NL][TB][RC];   // 24 KB prefetched slices
    __shared__ float s_co[TB][4 * RC];

    const int tid = threadIdx.x;
    const int b0  = blockIdx.x * TB;
    const int g   = tid >> 8;          // 0..1: handles rows t0, t0+1
    const int j   = tid & 255;
    const int t0  = g * 2;

    // ---- prefetch ALL 24 layers' dilated queue values into shared ----
    for (int idx = tid; idx < NL * TB * RC; idx += CTHREADS) {
        int i = idx >> 8;              // / (TB*RC)
        int t = (idx >> 6) & 3;
        int r = idx & 63;
        s_pv[i][t][r] = __ldg(queues
            + (((size_t)(b0 + t) * RC + r) + (size_t)i * LSTR) * QL
            + QL - (1 << (i & 7)));
    }

    // ---- initial h, c = tanh(inp @ W^T + b)  (threads 0..255) ----
    float* __restrict__ outq = out + BATCH;
    size_t ebase = 0;
    if (tid < TB * RC) {
        int t = tid >> 6, r = tid & 63;
        int b = b0 + t;
        ebase = (size_t)b * RC + r;
        const float* wh = fc_h_w + r * 33;
        const float* wc = fc_c_w + r * 33;
        float ah = fc_h_b[r], ac = fc_c_b[r];
        float xv = x[b];
        ah += xv * wh[0];
        ac += xv * wc[0];
        const float* fb = features + b * 32;
        #pragma unroll
        for (int k = 0; k < 32; k++) {
            float f = fb[k];
            ah += f * wh[1 + k];
            ac += f * wc[1 + k];
        }
        float h0 = tanhf(ah);
        s_h[t][r] = h0;
        s_c[t][r] = tanhf(ac);
        outq[ebase * 129 + QL] = h0;           // entry for layer 0
    }

    float yacc0 = fc1_b[j], yacc1 = yacc0;
    __syncthreads();

    const float4* __restrict__ wcv = g_convP + j;   // + (i*32+p)*256
    const float4* __restrict__ wf1 = g_fc1P  + j;   // + (i*16+q)*256

    for (int i = 0; i < NL; i++) {
        // ---- conv layer i (+ fused fc1 of layer i-1, same s_h reads) ----
        float acc0a, acc0b, acc1a, acc1b;
        acc0a = acc1a = __ldg(conv_b + i * 256 + j);
        acc0b = acc1b = 0.0f;
        const float4* wci = wcv + (size_t)i * (32 * 256);
        const float4* f1p = wf1 + (size_t)(i - 1) * (16 * 256);
        const bool addf = (i > 0);
        #pragma unroll 4
        for (int rc = 0; rc < RC; rc += 4) {
            float4 wA = __ldg(&wci[((rc >> 1)    ) << 8]);  // rc, rc+1
            float4 wB = __ldg(&wci[((rc >> 1) + 1) << 8]);  // rc+2, rc+3
            float4 fA = make_float4(0.f, 0.f, 0.f, 0.f);
            if (addf) fA = __ldg(&f1p[(rc >> 2) << 8]);
            {
                float4 p  = *(const float4*)&s_pv[i][t0][rc];
                float4 hh = *(const float4*)&s_h[t0][rc];
                acc0a += p.x * wA.x + hh.x * wA.y;
                acc0b += p.y * wA.z + hh.y * wA.w;
                acc0a += p.z * wB.x + hh.z * wB.y;
                acc0b += p.w * wB.z + hh.w * wB.w;
                yacc0 += hh.x * fA.x + hh.y * fA.y + hh.z * fA.z + hh.w * fA.w;
            }
            {
                float4 p  = *(const float4*)&s_pv[i][t0 + 1][rc];
                float4 hh = *(const float4*)&s_h[t0 + 1][rc];
                acc1a += p.x * wA.x + hh.x * wA.y;
                acc1b += p.y * wA.z + hh.y * wA.w;
                acc1a += p.z * wB.x + hh.z * wB.y;
                acc1b += p.w * wB.z + hh.w * wB.w;
                yacc1 += hh.x * fA.x + hh.y * fA.y + hh.z * fA.z + hh.w * fA.w;
            }
        }
        s_co[t0][j]     = acc0a + acc0b;
        s_co[t0 + 1][j] = acc1a + acc1b;
        __syncthreads();

        // ---- gate update (threads 0..255); write next layer's entry ----
        if (tid < TB * RC) {
            int t = tid >> 6, r = tid & 63;
            float ig = s_co[t][r];
            float cf = s_co[t][RC + r];
            float cg = s_co[t][2 * RC + r];
            float eg = s_co[t][3 * RC + r];
            float c = sigf(ig) * s_c[t][r] + tanhf(cf) * sigf(cg);
            float h = sigf(eg) * tanhf(c);
            s_c[t][r] = c;
            s_h[t][r] = h;
            if (i + 1 < NL)                    // entry_h for layer i+1
                outq[(ebase + (size_t)(i + 1) * LSTR) * 129 + QL] = h;
        }
        __syncthreads();
    }

    // ---- trailing fc1 for layer 23's skip-h ----
    {
        const float4* f1p = wf1 + (size_t)(NL - 1) * (16 * 256);
        #pragma unroll 4
        for (int rc = 0; rc < RC; rc += 4) {
            float4 fA = __ldg(&f1p[(rc >> 2) << 8]);
            {
                float4 hh = *(const float4*)&s_h[t0][rc];
                yacc0 += hh.x * fA.x + hh.y * fA.y + hh.z * fA.z + hh.w * fA.w;
            }
            {
                float4 hh = *(const float4*)&s_h[t0 + 1][rc];
                yacc1 += hh.x * fA.x + hh.y * fA.y + hh.z * fA.z + hh.w * fA.w;
            }
        }
    }

    // ---- fc2: h_hat[b] = relu(y) @ fc2_w^T + fc2_b ----
    __syncthreads();
    {
        float fw = fc2_w[j];
        s_co[t0][j]     = fmaxf(yacc0, 0.0f) * fw;
        s_co[t0 + 1][j] = fmaxf(yacc1, 0.0f) * fw;
    }
    __syncthreads();

    int w = tid >> 5, lane = tid & 31;
    if (w < TB) {                        // warps 0..3 reduce the TB rows
        float s = 0.0f;
        #pragma unroll
        for (int k = 0; k < 8; k++) s += s_co[w][lane + k * 32];
        #pragma unroll
        for (int o = 16; o > 0; o >>= 1) s += __shfl_xor_sync(0xffffffffu, s, o);
        if (lane == 0) out[b0 + w] = s + fc2_b[0];
    }
}

extern "C" void kernel_launch(void* const* d_in, const int* in_sizes, int n_in,
                              void* d_out, int out_size)
{
    const float* x        = (const float*)d_in[0];
    const float* features = (const float*)d_in[1];
    const float* queues   = (const float*)d_in[2];
    const float* fc_h_w   = (const float*)d_in[3];
    const float* fc_h_b   = (const float*)d_in[4];
    const float* fc_c_w   = (const float*)d_in[5];
    const float* fc_c_b   = (const float*)d_in[6];
    const float* conv_w   = (const float*)d_in[7];
    const float* conv_b   = (const float*)d_in[8];
    const float* fc1_w    = (const float*)d_in[9];
    const float* fc1_b    = (const float*)d_in[10];
    const float* fc2_w    = (const float*)d_in[11];
    const float* fc2_b    = (const float*)d_in[12];
    float* out = (float*)d_out;

    // Serial: transpose (tiny) -> compute (weights warm in L2) -> copy.
    transpose_weights_kernel<<<(NCONVP + NTHREADS - 1) / NTHREADS, NTHREADS>>>(
        conv_w, fc1_w);

    wave_compute_kernel<<<NCOMP, CTHREADS>>>(
        x, features, queues, fc_h_w, fc_h_b, fc_c_w, fc_c_b,
        conv_b, fc1_b, fc2_w, fc2_b, out);

    queue_copy_kernel<<<NCOPY, NTHREADS>>>(queues, out);
}

// round 11
// speedup vs baseline: 1.0058x; 1.0046x over previous
#include <cuda_runtime.h>

#define BATCH 1024
#define RC 64
#define NL 24
#define QL 128
#define TB 4                     // batch rows per compute block
#define NCOMP (BATCH / TB)       // 256 compute blocks
#define CTHREADS 512             // 2 groups of 256; each thread: 2 rows
#define NTHREADS 256
#define NQ ((size_t)NL * BATCH * RC * QL)   // 201326592 queue elements
#define NROWS (NQ / 128)                    // 1572864 rows of 128 floats
#define RPW 64                              // rows per copy warp
#define WARPS_PER_BLK 8
#define NCOPY ((int)(NROWS / (RPW * WARPS_PER_BLK)))   // 3072 copy blocks
#define LSTR ((size_t)BATCH * RC)           // row index stride per layer
#define NCONVP (NL * 32 * 256)              // packed conv float4 count
#define NFC1P  (NL * 16 * 256)              // packed fc1 float4 count

// Packed transposed weights, lane-coalesced for thread==j mapping.
__device__ float4 g_convP[NCONVP];   // [i][p][j] = (w0[2p],w1[2p],w0[2p+1],w1[2p+1])
__device__ float4 g_fc1P[NFC1P];     // [i][q][j] = fc1[rc=4q..4q+3]

__device__ __forceinline__ float sigf(float x) { return 1.0f / (1.0f + __expf(-x)); }

// ---------------------------------------------------------------------------
// WEIGHT TRANSPOSE (packed float4):
//   conv_w row (i,j) is 128 contiguous floats [rc][2]; float4 #p of that row
//   is exactly (w0[2p],w1[2p],w0[2p+1],w1[2p+1]).
//   fc1_w row j is 1536 contiguous floats; float4 #(i*16+q) is fc1[i][4q..4q+3].
// ---------------------------------------------------------------------------
__global__ void __launch_bounds__(NTHREADS)
transpose_weights_kernel(const float* __restrict__ conv_w,
                         const float* __restrict__ fc1_w)
{
    int idx = blockIdx.x * NTHREADS + threadIdx.x;   // ((i*32+p)*256+j)
    if (idx < NCONVP) {
        int j  = idx & 255;
        int pi = idx >> 8;           // i*32 + p
        int p  = pi & 31;
        int i  = pi >> 5;
        g_convP[idx] =
            __ldg((const float4*)(conv_w + (((size_t)i * 256 + j) << 7)) + p);
    }
    if (idx < NFC1P) {
        int j  = idx & 255;
        int qi = idx >> 8;           // i*16 + q
        g_fc1P[idx] =
            __ldg((const float4*)(fc1_w + (size_t)j * (NL * RC)) + qi);
    }
}

// Store one 128-float row (held as float4 v per lane) to dstq + R*129,
// realigned so the bulk goes out as one aligned STG.128 per lane.
__device__ __forceinline__ void store_row(float* __restrict__ dstq, size_t R,
                                          int lane, float4 v)
{
    float* base = dstq + R * 129;
    unsigned m = (unsigned)(R & 3);          // base misalignment in floats
    if (m == 0) {
        *(float4*)(base + 4 * lane) = v;
        return;
    }
    unsigned s = 4 - m;                      // shift: first aligned float index
    float nx = __shfl_down_sync(0xffffffffu, v.x, 1);
    float ny = __shfl_down_sync(0xffffffffu, v.y, 1);
    float nz = __shfl_down_sync(0xffffffffu, v.z, 1);
    float4 w;
    if (s == 1)      w = make_float4(v.y, v.z, v.w, nx);
    else if (s == 2) w = make_float4(v.z, v.w, nx, ny);
    else             w = make_float4(v.w, nx, ny, nz);
    if (lane < 31)
        *(float4*)(base + s + 4 * lane) = w; // 16B-aligned bulk
    if (lane == 0) {                         // head floats j = 0..s-1
        base[0] = v.x;
        if (s >= 2) base[1] = v.y;
        if (s >= 3) base[2] = v.z;
    }
    if (lane == 31) {                        // tail floats j = s+124..127
        base[127] = v.w;
        if (s <= 2) base[126] = v.z;
        if (s <= 1) base[125] = v.y;
    }
}

// ---------------------------------------------------------------------------
// COPY KERNEL: queues (.., 128) -> out queue region (.., 129), t < 128.
// (Proven: 313us standalone, 5.1 TB/s, occ 88%.)
// ---------------------------------------------------------------------------
__global__ void __launch_bounds__(NTHREADS)
queue_copy_kernel(const float* __restrict__ queues, float* __restrict__ out)
{
    const float4* __restrict__ src = (const float4*)queues;
    float* __restrict__ dstq = out + BATCH;
    const int lane = threadIdx.x & 31;
    size_t R = ((size_t)blockIdx.x * WARPS_PER_BLK + (threadIdx.x >> 5)) * RPW;

    #pragma unroll 1
    for (int it = 0; it < RPW / 4; it++, R += 4) {
        float4 v0 = __ldcs(&src[(R)     * 32 + lane]);
        float4 v1 = __ldcs(&src[(R + 1) * 32 + lane]);
        float4 v2 = __ldcs(&src[(R + 2) * 32 + lane]);
        float4 v3 = __ldcs(&src[(R + 3) * 32 + lane]);
        store_row(dstq, R,     lane, v0);
        store_row(dstq, R + 1, lane, v1);
        store_row(dstq, R + 2, lane, v2);
        store_row(dstq, R + 3, lane, v3);
    }
}

// ---------------------------------------------------------------------------
// COMPUTE KERNEL: 512 threads, TB=4 rows (R8 shape). Group g = tid>>8
// handles rows {2g, 2g+1} with channel j = tid&255. fc1 of layer i-1 is
// fused into layer i's conv loop. Weights read as packed float4 (3 LDG.128
// per 4-rc block instead of 8 loads).
// ---------------------------------------------------------------------------
__global__ void __launch_bounds__(CTHREADS, 2)
wave_compute_kernel(const float* __restrict__ x,
                    const float* __restrict__ features,
                    const float* __restrict__ queues,
                    const float* __restrict__ fc_h_w,
                    const float* __restrict__ fc_h_b,
                    const float* __restrict__ fc_c_w,
                    const float* __restrict__ fc_c_b,
                    const float* __restrict__ conv_b,
                    const float* __restrict__ fc1_b,
                    const float* __restrict__ fc2_w,
                    const float* __restrict__ fc2_b,
                    float* __restrict__ out)
{
    __shared__ __align__(16) float s_h[TB][RC];
    __shared__ __align__(16) float s_c[TB][RC];
    __shared__ __align__(16) float s_pv[NL][TB][RC];   // 24 KB prefetched slices
    __shared__ float s_co[TB][4 * RC];

    const int tid = threadIdx.x;
    const int b0  = blockIdx.x * TB;
    const int g   = tid >> 8;          // 0..1: handles rows t0, t0+1
    const int j   = tid & 255;
    const int t0  = g * 2;

    // ---- prefetch ALL 24 layers' dilated queue values into shared ----
    for (int idx = tid; idx < NL * TB * RC; idx += CTHREADS) {
        int i = idx >> 8;              // / (TB*RC)
        int t = (idx >> 6) & 3;
        int r = idx & 63;
        s_pv[i][t][r] = __ldg(queues
            + (((size_t)(b0 + t) * RC + r) + (size_t)i * LSTR) * QL
            + QL - (1 << (i & 7)));
    }

    // ---- initial h, c = tanh(inp @ W^T + b)  (threads 0..255) ----
    float* __restrict__ outq = out + BATCH;
    size_t ebase = 0;
    if (tid < TB * RC) {
        int t = tid >> 6, r = tid & 63;
        int b = b0 + t;
        ebase = (size_t)b * RC + r;
        const float* wh = fc_h_w + r * 33;
        const float* wc = fc_c_w + r * 33;
        float ah = fc_h_b[r], ac = fc_c_b[r];
        float xv = x[b];
        ah += xv * wh[0];
        ac += xv * wc[0];
        const float* fb = features + b * 32;
        #pragma unroll
        for (int k = 0; k < 32; k++) {
            float f = fb[k];
            ah += f * wh[1 + k];
            ac += f * wc[1 + k];
        }
        float h0 = tanhf(ah);
        s_h[t][r] = h0;
        s_c[t][r] = tanhf(ac);
        outq[ebase * 129 + QL] = h0;           // entry for layer 0
    }

    float yacc0 = fc1_b[j], yacc1 = yacc0;
    __syncthreads();

    const float4* __restrict__ wcv = g_convP + j;   // + (i*32+p)*256
    const float4* __restrict__ wf1 = g_fc1P  + j;   // + (i*16+q)*256

    for (int i = 0; i < NL; i++) {
        // ---- conv layer i (+ fused fc1 of layer i-1, same s_h reads) ----
        float acc0a, acc0b, acc1a, acc1b;
        acc0a = acc1a = __ldg(conv_b + i * 256 + j);
        acc0b = acc1b = 0.0f;
        const float4* wci = wcv + (size_t)i * (32 * 256);
        const float4* f1p = wf1 + (size_t)(i - 1) * (16 * 256);
        const bool addf = (i > 0);
        #pragma unroll 4
        for (int rc = 0; rc < RC; rc += 4) {
            float4 wA = __ldg(&wci[((rc >> 1)    ) << 8]);  // rc, rc+1
            float4 wB = __ldg(&wci[((rc >> 1) + 1) << 8]);  // rc+2, rc+3
            float4 fA = make_float4(0.f, 0.f, 0.f, 0.f);
            if (addf) fA = __ldg(&f1p[(rc >> 2) << 8]);
            {
                float4 p  = *(const float4*)&s_pv[i][t0][rc];
                float4 hh = *(const float4*)&s_h[t0][rc];
                acc0a += p.x * wA.x + hh.x * wA.y;
                acc0b += p.y * wA.z + hh.y * wA.w;
                acc0a += p.z * wB.x + hh.z * wB.y;
                acc0b += p.w * wB.z + hh.w * wB.w;
                yacc0 += hh.x * fA.x + hh.y * fA.y + hh.z * fA.z + hh.w * fA.w;
            }
            {
                float4 p  = *(const float4*)&s_pv[i][t0 + 1][rc];
                float4 hh = *(const float4*)&s_h[t0 + 1][rc];
                acc1a += p.x * wA.x + hh.x * wA.y;
                acc1b += p.y * wA.z + hh.y * wA.w;
                acc1a += p.z * wB.x + hh.z * wB.y;
                acc1b += p.w * wB.z + hh.w * wB.w;
                yacc1 += hh.x * fA.x + hh.y * fA.y + hh.z * fA.z + hh.w * fA.w;
            }
        }
        s_co[t0][j]     = acc0a + acc0b;
        s_co[t0 + 1][j] = acc1a + acc1b;
        __syncthreads();

        // ---- gate update (threads 0..255); write next layer's entry ----
        if (tid < TB * RC) {
            int t = tid >> 6, r = tid & 63;
            float ig = s_co[t][r];
            float cf = s_co[t][RC + r];
            float cg = s_co[t][2 * RC + r];
            float eg = s_co[t][3 * RC + r];
            float c = sigf(ig) * s_c[t][r] + tanhf(cf) * sigf(cg);
            float h = sigf(eg) * tanhf(c);
            s_c[t][r] = c;
            s_h[t][r] = h;
            if (i + 1 < NL)                    // entry_h for layer i+1
                outq[(ebase + (size_t)(i + 1) * LSTR) * 129 + QL] = h;
        }
        __syncthreads();
    }

    // ---- trailing fc1 for layer 23's skip-h ----
    {
        const float4* f1p = wf1 + (size_t)(NL - 1) * (16 * 256);
        #pragma unroll 4
        for (int rc = 0; rc < RC; rc += 4) {
            float4 fA = __ldg(&f1p[(rc >> 2) << 8]);
            {
                float4 hh = *(const float4*)&s_h[t0][rc];
                yacc0 += hh.x * fA.x + hh.y * fA.y + hh.z * fA.z + hh.w * fA.w;
            }
            {
                float4 hh = *(const float4*)&s_h[t0 + 1][rc];
                yacc1 += hh.x * fA.x + hh.y * fA.y + hh.z * fA.z + hh.w * fA.w;
            }
        }
    }

    // ---- fc2: h_hat[b] = relu(y) @ fc2_w^T + fc2_b ----
    __syncthreads();
    {
        float fw = fc2_w[j];
        s_co[t0][j]     = fmaxf(yacc0, 0.0f) * fw;
        s_co[t0 + 1][j] = fmaxf(yacc1, 0.0f) * fw;
    }
    __syncthreads();

    int w = tid >> 5, lane = tid & 31;
    if (w < TB) {                        // warps 0..3 reduce the TB rows
        float s = 0.0f;
        #pragma unroll
        for (int k = 0; k < 8; k++) s += s_co[w][lane + k * 32];
        #pragma unroll
        for (int o = 16; o > 0; o >>= 1) s += __shfl_xor_sync(0xffffffffu, s, o);
        if (lane == 0) out[b0 + w] = s + fc2_b[0];
    }
}

extern "C" void kernel_launch(void* const* d_in, const int* in_sizes, int n_in,
                              void* d_out, int out_size)
{
    const float* x        = (const float*)d_in[0];
    const float* features = (const float*)d_in[1];
    const float* queues   = (const float*)d_in[2];
    const float* fc_h_w   = (const float*)d_in[3];
    const float* fc_h_b   = (const float*)d_in[4];
    const float* fc_c_w   = (const float*)d_in[5];
    const float* fc_c_b   = (const float*)d_in[6];
    const float* conv_w   = (const float*)d_in[7];
    const float* conv_b   = (const float*)d_in[8];
    const float* fc1_w    = (const float*)d_in[9];
    const float* fc1_b    = (const float*)d_in[10];
    const float* fc2_w    = (const float*)d_in[11];
    const float* fc2_b    = (const float*)d_in[12];
    float* out = (float*)d_out;

    // Serial: transpose (tiny) -> compute (weights warm in L2) -> copy.
    transpose_weights_kernel<<<(NCONVP + NTHREADS - 1) / NTHREADS, NTHREADS>>>(
        conv_w, fc1_w);

    wave_compute_kernel<<<NCOMP, CTHREADS>>>(
        x, features, queues, fc_h_w, fc_h_b, fc_c_w, fc_c_b,
        conv_b, fc1_b, fc2_w, fc2_b, out);

    queue_copy_kernel<<<NCOPY, NTHREADS>>>(queues, out);
}

// round 12
// speedup vs baseline: 1.0063x; 1.0005x over previous
#include <cuda_runtime.h>

#define BATCH 1024
#define RC 64
#define NL 24
#define QL 128
#define TB 4                     // batch rows per compute block
#define NCOMP (BATCH / TB)       // 256 compute blocks
#define CTHREADS 512             // 2 groups of 256; each thread: 2 rows
#define NTHREADS 256
#define NQ ((size_t)NL * BATCH * RC * QL)   // 201326592 queue elements
#define NROWS (NQ / 128)                    // 1572864 rows of 128 floats
#define RPW 64                              // rows per copy warp
#define WARPS_PER_BLK 8
#define NCOPY ((int)(NROWS / (RPW * WARPS_PER_BLK)))   // 3072 copy blocks
#define LSTR ((size_t)BATCH * RC)           // row index stride per layer
#define NCONVP (NL * 32 * 256)              // packed conv float4 count
#define NFC1P  (NL * 16 * 256)              // packed fc1 float4 count

// Packed transposed weights, lane-coalesced for thread==j mapping.
__device__ float4 g_convP[NCONVP];   // [i][p][j] = (w0[2p],w1[2p],w0[2p+1],w1[2p+1])
__device__ float4 g_fc1P[NFC1P];     // [i][q][j] = fc1[rc=4q..4q+3]

__device__ __forceinline__ float sigf(float x) { return 1.0f / (1.0f + __expf(-x)); }

// ---------------------------------------------------------------------------
// WEIGHT TRANSPOSE (packed float4):
//   conv_w row (i,j) is 128 contiguous floats [rc][2]; float4 #p of that row
//   is exactly (w0[2p],w1[2p],w0[2p+1],w1[2p+1]).
//   fc1_w row j is 1536 contiguous floats; float4 #(i*16+q) is fc1[i][4q..4q+3].
// ---------------------------------------------------------------------------
__global__ void __launch_bounds__(NTHREADS)
transpose_weights_kernel(const float* __restrict__ conv_w,
                         const float* __restrict__ fc1_w)
{
    int idx = blockIdx.x * NTHREADS + threadIdx.x;   // ((i*32+p)*256+j)
    if (idx < NCONVP) {
        int j  = idx & 255;
        int pi = idx >> 8;           // i*32 + p
        int p  = pi & 31;
        int i  = pi >> 5;
        g_convP[idx] =
            __ldg((const float4*)(conv_w + (((size_t)i * 256 + j) << 7)) + p);
    }
    if (idx < NFC1P) {
        int j  = idx & 255;
        int qi = idx >> 8;           // i*16 + q
        g_fc1P[idx] =
            __ldg((const float4*)(fc1_w + (size_t)j * (NL * RC)) + qi);
    }
}

// Store one 128-float row (held as float4 v per lane) to dstq + R*129,
// realigned so the bulk goes out as one aligned STG.128 per lane.
__device__ __forceinline__ void store_row(float* __restrict__ dstq, size_t R,
                                          int lane, float4 v)
{
    float* base = dstq + R * 129;
    unsigned m = (unsigned)(R & 3);          // base misalignment in floats
    if (m == 0) {
        *(float4*)(base + 4 * lane) = v;
        return;
    }
    unsigned s = 4 - m;                      // shift: first aligned float index
    float nx = __shfl_down_sync(0xffffffffu, v.x, 1);
    float ny = __shfl_down_sync(0xffffffffu, v.y, 1);
    float nz = __shfl_down_sync(0xffffffffu, v.z, 1);
    float4 w;
    if (s == 1)      w = make_float4(v.y, v.z, v.w, nx);
    else if (s == 2) w = make_float4(v.z, v.w, nx, ny);
    else             w = make_float4(v.w, nx, ny, nz);
    if (lane < 31)
        *(float4*)(base + s + 4 * lane) = w; // 16B-aligned bulk
    if (lane == 0) {                         // head floats j = 0..s-1
        base[0] = v.x;
        if (s >= 2) base[1] = v.y;
        if (s >= 3) base[2] = v.z;
    }
    if (lane == 31) {                        // tail floats j = s+124..127
        base[127] = v.w;
        if (s <= 2) base[126] = v.z;
        if (s <= 1) base[125] = v.y;
    }
}

// ---------------------------------------------------------------------------
// COPY KERNEL: queues (.., 128) -> out queue region (.., 129), t < 128.
// (Proven: 313us standalone, 5.1 TB/s, occ 88%.)
// ---------------------------------------------------------------------------
__global__ void __launch_bounds__(NTHREADS)
queue_copy_kernel(const float* __restrict__ queues, float* __restrict__ out)
{
    const float4* __restrict__ src = (const float4*)queues;
    float* __restrict__ dstq = out + BATCH;
    const int lane = threadIdx.x & 31;
    size_t R = ((size_t)blockIdx.x * WARPS_PER_BLK + (threadIdx.x >> 5)) * RPW;

    #pragma unroll 1
    for (int it = 0; it < RPW / 4; it++, R += 4) {
        float4 v0 = __ldcs(&src[(R)     * 32 + lane]);
        float4 v1 = __ldcs(&src[(R + 1) * 32 + lane]);
        float4 v2 = __ldcs(&src[(R + 2) * 32 + lane]);
        float4 v3 = __ldcs(&src[(R + 3) * 32 + lane]);
        store_row(dstq, R,     lane, v0);
        store_row(dstq, R + 1, lane, v1);
        store_row(dstq, R + 2, lane, v2);
        store_row(dstq, R + 3, lane, v3);
    }
}

// ---------------------------------------------------------------------------
// COMPUTE KERNEL: 512 threads, TB=4 rows (R8 shape). Group g = tid>>8
// handles rows {2g, 2g+1} with channel j = tid&255. fc1 of layer i-1 is
// fused into layer i's conv loop. Weights read as packed float4 (3 LDG.128
// per 4-rc block instead of 8 loads).
// ---------------------------------------------------------------------------
__global__ void __launch_bounds__(CTHREADS, 2)
wave_compute_kernel(const float* __restrict__ x,
                    const float* __restrict__ features,
                    const float* __restrict__ queues,
                    const float* __restrict__ fc_h_w,
                    const float* __restrict__ fc_h_b,
                    const float* __restrict__ fc_c_w,
                    const float* __restrict__ fc_c_b,
                    const float* __restrict__ conv_b,
                    const float* __restrict__ fc1_b,
                    const float* __restrict__ fc2_w,
                    const float* __restrict__ fc2_b,
                    float* __restrict__ out)
{
    __shared__ __align__(16) float s_h[TB][RC];
    __shared__ __align__(16) float s_c[TB][RC];
    __shared__ __align__(16) float s_pv[NL][TB][RC];   // 24 KB prefetched slices
    __shared__ float s_co[TB][4 * RC];

    const int tid = threadIdx.x;
    const int b0  = blockIdx.x * TB;
    const int g   = tid >> 8;          // 0..1: handles rows t0, t0+1
    const int j   = tid & 255;
    const int t0  = g * 2;

    // ---- prefetch ALL 24 layers' dilated queue values into shared ----
    for (int idx = tid; idx < NL * TB * RC; idx += CTHREADS) {
        int i = idx >> 8;              // / (TB*RC)
        int t = (idx >> 6) & 3;
        int r = idx & 63;
        s_pv[i][t][r] = __ldg(queues
            + (((size_t)(b0 + t) * RC + r) + (size_t)i * LSTR) * QL
            + QL - (1 << (i & 7)));
    }

    // ---- initial h, c = tanh(inp @ W^T + b)  (threads 0..255) ----
    float* __restrict__ outq = out + BATCH;
    size_t ebase = 0;
    if (tid < TB * RC) {
        int t = tid >> 6, r = tid & 63;
        int b = b0 + t;
        ebase = (size_t)b * RC + r;
        const float* wh = fc_h_w + r * 33;
        const float* wc = fc_c_w + r * 33;
        float ah = fc_h_b[r], ac = fc_c_b[r];
        float xv = x[b];
        ah += xv * wh[0];
        ac += xv * wc[0];
        const float* fb = features + b * 32;
        #pragma unroll
        for (int k = 0; k < 32; k++) {
            float f = fb[k];
            ah += f * wh[1 + k];
            ac += f * wc[1 + k];
        }
        float h0 = tanhf(ah);
        s_h[t][r] = h0;
        s_c[t][r] = tanhf(ac);
        outq[ebase * 129 + QL] = h0;           // entry for layer 0
    }

    float yacc0 = fc1_b[j], yacc1 = yacc0;
    __syncthreads();

    const float4* __restrict__ wcv = g_convP + j;   // + (i*32+p)*256
    const float4* __restrict__ wf1 = g_fc1P  + j;   // + (i*16+q)*256

    for (int i = 0; i < NL; i++) {
        // ---- conv layer i (+ fused fc1 of layer i-1, same s_h reads) ----
        float acc0a, acc0b, acc1a, acc1b;
        acc0a = acc1a = __ldg(conv_b + i * 256 + j);
        acc0b = acc1b = 0.0f;
        const float4* wci = wcv + (size_t)i * (32 * 256);
        const float4* f1p = wf1 + (size_t)(i - 1) * (16 * 256);
        const bool addf = (i > 0);
        #pragma unroll 4
        for (int rc = 0; rc < RC; rc += 4) {
            float4 wA = __ldg(&wci[((rc >> 1)    ) << 8]);  // rc, rc+1
            float4 wB = __ldg(&wci[((rc >> 1) + 1) << 8]);  // rc+2, rc+3
            float4 fA = make_float4(0.f, 0.f, 0.f, 0.f);
            if (addf) fA = __ldg(&f1p[(rc >> 2) << 8]);
            {
                float4 p  = *(const float4*)&s_pv[i][t0][rc];
                float4 hh = *(const float4*)&s_h[t0][rc];
                acc0a += p.x * wA.x + hh.x * wA.y;
                acc0b += p.y * wA.z + hh.y * wA.w;
                acc0a += p.z * wB.x + hh.z * wB.y;
                acc0b += p.w * wB.z + hh.w * wB.w;
                yacc0 += hh.x * fA.x + hh.y * fA.y + hh.z * fA.z + hh.w * fA.w;
            }
            {
                float4 p  = *(const float4*)&s_pv[i][t0 + 1][rc];
                float4 hh = *(const float4*)&s_h[t0 + 1][rc];
                acc1a += p.x * wA.x + hh.x * wA.y;
                acc1b += p.y * wA.z + hh.y * wA.w;
                acc1a += p.z * wB.x + hh.z * wB.y;
                acc1b += p.w * wB.z + hh.w * wB.w;
                yacc1 += hh.x * fA.x + hh.y * fA.y + hh.z * fA.z + hh.w * fA.w;
            }
        }
        s_co[t0][j]     = acc0a + acc0b;
        s_co[t0 + 1][j] = acc1a + acc1b;
        __syncthreads();

        // ---- gate update (threads 0..255); write next layer's entry ----
        if (tid < TB * RC) {
            int t = tid >> 6, r = tid & 63;
            float ig = s_co[t][r];
            float cf = s_co[t][RC + r];
            float cg = s_co[t][2 * RC + r];
            float eg = s_co[t][3 * RC + r];
            float c = sigf(ig) * s_c[t][r] + tanhf(cf) * sigf(cg);
            float h = sigf(eg) * tanhf(c);
            s_c[t][r] = c;
            s_h[t][r] = h;
            if (i + 1 < NL)                    // entry_h for layer i+1
                outq[(ebase + (size_t)(i + 1) * LSTR) * 129 + QL] = h;
        }
        __syncthreads();
    }

    // ---- trailing fc1 for layer 23's skip-h ----
    {
        const float4* f1p = wf1 + (size_t)(NL - 1) * (16 * 256);
        #pragma unroll 4
        for (int rc = 0; rc < RC; rc += 4) {
            float4 fA = __ldg(&f1p[(rc >> 2) << 8]);
            {
                float4 hh = *(const float4*)&s_h[t0][rc];
                yacc0 += hh.x * fA.x + hh.y * fA.y + hh.z * fA.z + hh.w * fA.w;
            }
            {
                float4 hh = *(const float4*)&s_h[t0 + 1][rc];
                yacc1 += hh.x * fA.x + hh.y * fA.y + hh.z * fA.z + hh.w * fA.w;
            }
        }
    }

    // ---- fc2: h_hat[b] = relu(y) @ fc2_w^T + fc2_b ----
    __syncthreads();
    {
        float fw = fc2_w[j];
        s_co[t0][j]     = fmaxf(yacc0, 0.0f) * fw;
        s_co[t0 + 1][j] = fmaxf(yacc1, 0.0f) * fw;
    }
    __syncthreads();

    int w = tid >> 5, lane = tid & 31;
    if (w < TB) {                        // warps 0..3 reduce the TB rows
        float s = 0.0f;
        #pragma unroll
        for (int k = 0; k < 8; k++) s += s_co[w][lane + k * 32];
        #pragma unroll
        for (int o = 16; o > 0; o >>= 1) s += __shfl_xor_sync(0xffffffffu, s, o);
        if (lane == 0) out[b0 + w] = s + fc2_b[0];
    }
}

extern "C" void kernel_launch(void* const* d_in, const int* in_sizes, int n_in,
                              void* d_out, int out_size)
{
    const float* x        = (const float*)d_in[0];
    const float* features = (const float*)d_in[1];
    const float* queues   = (const float*)d_in[2];
    const float* fc_h_w   = (const float*)d_in[3];
    const float* fc_h_b   = (const float*)d_in[4];
    const float* fc_c_w   = (const float*)d_in[5];
    const float* fc_c_b   = (const float*)d_in[6];
    const float* conv_w   = (const float*)d_in[7];
    const float* conv_b   = (const float*)d_in[8];
    const float* fc1_w    = (const float*)d_in[9];
    const float* fc1_b    = (const float*)d_in[10];
    const float* fc2_w    = (const float*)d_in[11];
    const float* fc2_b    = (const float*)d_in[12];
    float* out = (float*)d_out;

    // Serial: transpose (tiny) -> compute (weights warm in L2) -> copy.
    transpose_weights_kernel<<<(NCONVP + NTHREADS - 1) / NTHREADS, NTHREADS>>>(
        conv_w, fc1_w);

    wave_compute_kernel<<<NCOMP, CTHREADS>>>(
        x, features, queues, fc_h_w, fc_h_b, fc_c_w, fc_c_b,
        conv_b, fc1_b, fc2_w, fc2_b, out);

    queue_copy_kernel<<<NCOPY, NTHREADS>>>(queues, out);
}

// round 13
// speedup vs baseline: 1.0160x; 1.0097x over previous
#include <cuda_runtime.h>

#define BATCH 1024
#define RC 64
#define NL 24
#define QL 128
#define TB 4                     // batch rows per compute block
#define NCOMP (BATCH / TB)       // 256 compute blocks
#define CTHREADS 512             // 2 groups of 256; each thread: 2 rows
#define NTHREADS 256
#define NQ ((size_t)NL * BATCH * RC * QL)   // 201326592 queue elements
#define NROWS (NQ / 128)                    // 1572864 rows of 128 floats
#define RPW 64                              // rows per copy warp
#define WARPS_PER_BLK 8
#define NCOPY ((int)(NROWS / (RPW * WARPS_PER_BLK)))   // 3072 copy blocks
#define LSTR ((size_t)BATCH * RC)           // row index stride per layer
#define NCONVP (NL * 32 * 256)              // packed conv float4 count
#define NFC1P  (NL * 16 * 256)              // packed fc1 float4 count

// Packed transposed weights, lane-coalesced for thread==j mapping.
__device__ float4 g_convP[NCONVP];   // [i][p][j] = (w0[2p],w1[2p],w0[2p+1],w1[2p+1])
__device__ float4 g_fc1P[NFC1P];     // [i][q][j] = fc1[rc=4q..4q+3]

__device__ __forceinline__ float sigf(float x) { return 1.0f / (1.0f + __expf(-x)); }

// ---------------------------------------------------------------------------
// WEIGHT TRANSPOSE (packed float4)
// ---------------------------------------------------------------------------
__global__ void __launch_bounds__(NTHREADS)
transpose_weights_kernel(const float* __restrict__ conv_w,
                         const float* __restrict__ fc1_w)
{
    int idx = blockIdx.x * NTHREADS + threadIdx.x;   // ((i*32+p)*256+j)
    if (idx < NCONVP) {
        int j  = idx & 255;
        int pi = idx >> 8;           // i*32 + p
        int p  = pi & 31;
        int i  = pi >> 5;
        g_convP[idx] =
            __ldg((const float4*)(conv_w + (((size_t)i * 256 + j) << 7)) + p);
    }
    if (idx < NFC1P) {
        int j  = idx & 255;
        int qi = idx >> 8;           // i*16 + q
        g_fc1P[idx] =
            __ldg((const float4*)(fc1_w + (size_t)j * (NL * RC)) + qi);
    }
}

// Store one 128-float row (held as float4 v per lane) to dstq + R*129,
// realigned so the bulk goes out as one aligned STG.128 per lane.
__device__ __forceinline__ void store_row(float* __restrict__ dstq, size_t R,
                                          int lane, float4 v)
{
    float* base = dstq + R * 129;
    unsigned m = (unsigned)(R & 3);          // base misalignment in floats
    if (m == 0) {
        *(float4*)(base + 4 * lane) = v;
        return;
    }
    unsigned s = 4 - m;                      // shift: first aligned float index
    float nx = __shfl_down_sync(0xffffffffu, v.x, 1);
    float ny = __shfl_down_sync(0xffffffffu, v.y, 1);
    float nz = __shfl_down_sync(0xffffffffu, v.z, 1);
    float4 w;
    if (s == 1)      w = make_float4(v.y, v.z, v.w, nx);
    else if (s == 2) w = make_float4(v.z, v.w, nx, ny);
    else             w = make_float4(v.w, nx, ny, nz);
    if (lane < 31)
        *(float4*)(base + s + 4 * lane) = w; // 16B-aligned bulk
    if (lane == 0) {                         // head floats j = 0..s-1
        base[0] = v.x;
        if (s >= 2) base[1] = v.y;
        if (s >= 3) base[2] = v.z;
    }
    if (lane == 31) {                        // tail floats j = s+124..127
        base[127] = v.w;
        if (s <= 2) base[126] = v.z;
        if (s <= 1) base[125] = v.y;
    }
}

// ---------------------------------------------------------------------------
// COPY KERNEL: queues (.., 128) -> out queue region (.., 129), t < 128.
// (Proven: 313us standalone, 5.1 TB/s, occ 88%.)
// ---------------------------------------------------------------------------
__global__ void __launch_bounds__(NTHREADS)
queue_copy_kernel(const float* __restrict__ queues, float* __restrict__ out)
{
    const float4* __restrict__ src = (const float4*)queues;
    float* __restrict__ dstq = out + BATCH;
    const int lane = threadIdx.x & 31;
    size_t R = ((size_t)blockIdx.x * WARPS_PER_BLK + (threadIdx.x >> 5)) * RPW;

    #pragma unroll 1
    for (int it = 0; it < RPW / 4; it++, R += 4) {
        float4 v0 = __ldcs(&src[(R)     * 32 + lane]);
        float4 v1 = __ldcs(&src[(R + 1) * 32 + lane]);
        float4 v2 = __ldcs(&src[(R + 2) * 32 + lane]);
        float4 v3 = __ldcs(&src[(R + 3) * 32 + lane]);
        store_row(dstq, R,     lane, v0);
        store_row(dstq, R + 1, lane, v1);
        store_row(dstq, R + 2, lane, v2);
        store_row(dstq, R + 3, lane, v3);
    }
}

// ---------------------------------------------------------------------------
// COMPUTE KERNEL: 512 threads, TB=4 rows. Group g = tid>>8 handles rows
// {2g, 2g+1} with channel j = tid&255. fc1 of layer i-1 fused into layer
// i's conv loop; packed float4 weights. (~278us standalone, low DRAM.)
// ---------------------------------------------------------------------------
__global__ void __launch_bounds__(CTHREADS, 2)
wave_compute_kernel(const float* __restrict__ x,
                    const float* __restrict__ features,
                    const float* __restrict__ queues,
                    const float* __restrict__ fc_h_w,
                    const float* __restrict__ fc_h_b,
                    const float* __restrict__ fc_c_w,
                    const float* __restrict__ fc_c_b,
                    const float* __restrict__ conv_b,
                    const float* __restrict__ fc1_b,
                    const float* __restrict__ fc2_w,
                    const float* __restrict__ fc2_b,
                    float* __restrict__ out)
{
    __shared__ __align__(16) float s_h[TB][RC];
    __shared__ __align__(16) float s_c[TB][RC];
    __shared__ __align__(16) float s_pv[NL][TB][RC];   // 24 KB prefetched slices
    __shared__ float s_co[TB][4 * RC];

    const int tid = threadIdx.x;
    const int b0  = blockIdx.x * TB;
    const int g   = tid >> 8;          // 0..1: handles rows t0, t0+1
    const int j   = tid & 255;
    const int t0  = g * 2;

    // ---- prefetch ALL 24 layers' dilated queue values into shared ----
    for (int idx = tid; idx < NL * TB * RC; idx += CTHREADS) {
        int i = idx >> 8;              // / (TB*RC)
        int t = (idx >> 6) & 3;
        int r = idx & 63;
        s_pv[i][t][r] = __ldg(queues
            + (((size_t)(b0 + t) * RC + r) + (size_t)i * LSTR) * QL
            + QL - (1 << (i & 7)));
    }

    // ---- initial h, c = tanh(inp @ W^T + b)  (threads 0..255) ----
    float* __restrict__ outq = out + BATCH;
    size_t ebase = 0;
    if (tid < TB * RC) {
        int t = tid >> 6, r = tid & 63;
        int b = b0 + t;
        ebase = (size_t)b * RC + r;
        const float* wh = fc_h_w + r * 33;
        const float* wc = fc_c_w + r * 33;
        float ah = fc_h_b[r], ac = fc_c_b[r];
        float xv = x[b];
        ah += xv * wh[0];
        ac += xv * wc[0];
        const float* fb = features + b * 32;
        #pragma unroll
        for (int k = 0; k < 32; k++) {
            float f = fb[k];
            ah += f * wh[1 + k];
            ac += f * wc[1 + k];
        }
        float h0 = tanhf(ah);
        s_h[t][r] = h0;
        s_c[t][r] = tanhf(ac);
        outq[ebase * 129 + QL] = h0;           // entry for layer 0
    }

    float yacc0 = fc1_b[j], yacc1 = yacc0;
    __syncthreads();

    const float4* __restrict__ wcv = g_convP + j;   // + (i*32+p)*256
    const float4* __restrict__ wf1 = g_fc1P  + j;   // + (i*16+q)*256

    for (int i = 0; i < NL; i++) {
        // ---- conv layer i (+ fused fc1 of layer i-1, same s_h reads) ----
        float acc0a, acc0b, acc1a, acc1b;
        acc0a = acc1a = __ldg(conv_b + i * 256 + j);
        acc0b = acc1b = 0.0f;
        const float4* wci = wcv + (size_t)i * (32 * 256);
        const float4* f1p = wf1 + (size_t)(i - 1) * (16 * 256);
        const bool addf = (i > 0);
        #pragma unroll 4
        for (int rc = 0; rc < RC; rc += 4) {
            float4 wA = __ldg(&wci[((rc >> 1)    ) << 8]);  // rc, rc+1
            float4 wB = __ldg(&wci[((rc >> 1) + 1) << 8]);  // rc+2, rc+3
            float4 fA = make_float4(0.f, 0.f, 0.f, 0.f);
            if (addf) fA = __ldg(&f1p[(rc >> 2) << 8]);
            {
                float4 p  = *(const float4*)&s_pv[i][t0][rc];
                float4 hh = *(const float4*)&s_h[t0][rc];
                acc0a += p.x * wA.x + hh.x * wA.y;
                acc0b += p.y * wA.z + hh.y * wA.w;
                acc0a += p.z * wB.x + hh.z * wB.y;
                acc0b += p.w * wB.z + hh.w * wB.w;
                yacc0 += hh.x * fA.x + hh.y * fA.y + hh.z * fA.z + hh.w * fA.w;
            }
            {
                float4 p  = *(const float4*)&s_pv[i][t0 + 1][rc];
                float4 hh = *(const float4*)&s_h[t0 + 1][rc];
                acc1a += p.x * wA.x + hh.x * wA.y;
                acc1b += p.y * wA.z + hh.y * wA.w;
                acc1a += p.z * wB.x + hh.z * wB.y;
                acc1b += p.w * wB.z + hh.w * wB.w;
                yacc1 += hh.x * fA.x + hh.y * fA.y + hh.z * fA.z + hh.w * fA.w;
            }
        }
        s_co[t0][j]     = acc0a + acc0b;
        s_co[t0 + 1][j] = acc1a + acc1b;
        __syncthreads();

        // ---- gate update (threads 0..255); write next layer's entry ----
        if (tid < TB * RC) {
            int t = tid >> 6, r = tid & 63;
            float ig = s_co[t][r];
            float cf = s_co[t][RC + r];
            float cg = s_co[t][2 * RC + r];
            float eg = s_co[t][3 * RC + r];
            float c = sigf(ig) * s_c[t][r] + tanhf(cf) * sigf(cg);
            float h = sigf(eg) * tanhf(c);
            s_c[t][r] = c;
            s_h[t][r] = h;
            if (i + 1 < NL)                    // entry_h for layer i+1
                outq[(ebase + (size_t)(i + 1) * LSTR) * 129 + QL] = h;
        }
        __syncthreads();
    }

    // ---- trailing fc1 for layer 23's skip-h ----
    {
        const float4* f1p = wf1 + (size_t)(NL - 1) * (16 * 256);
        #pragma unroll 4
        for (int rc = 0; rc < RC; rc += 4) {
            float4 fA = __ldg(&f1p[(rc >> 2) << 8]);
            {
                float4 hh = *(const float4*)&s_h[t0][rc];
                yacc0 += hh.x * fA.x + hh.y * fA.y + hh.z * fA.z + hh.w * fA.w;
            }
            {
                float4 hh = *(const float4*)&s_h[t0 + 1][rc];
                yacc1 += hh.x * fA.x + hh.y * fA.y + hh.z * fA.z + hh.w * fA.w;
            }
        }
    }

    // ---- fc2: h_hat[b] = relu(y) @ fc2_w^T + fc2_b ----
    __syncthreads();
    {
        float fw = fc2_w[j];
        s_co[t0][j]     = fmaxf(yacc0, 0.0f) * fw;
        s_co[t0 + 1][j] = fmaxf(yacc1, 0.0f) * fw;
    }
    __syncthreads();

    int w = tid >> 5, lane = tid & 31;
    if (w < TB) {                        // warps 0..3 reduce the TB rows
        float s = 0.0f;
        #pragma unroll
        for (int k = 0; k < 8; k++) s += s_co[w][lane + k * 32];
        #pragma unroll
        for (int o = 16; o > 0; o >>= 1) s += __shfl_xor_sync(0xffffffffu, s, o);
        if (lane == 0) out[b0 + w] = s + fc2_b[0];
    }
}

extern "C" void kernel_launch(void* const* d_in, const int* in_sizes, int n_in,
                              void* d_out, int out_size)
{
    const float* x        = (const float*)d_in[0];
    const float* features = (const float*)d_in[1];
    const float* queues   = (const float*)d_in[2];
    const float* fc_h_w   = (const float*)d_in[3];
    const float* fc_h_b   = (const float*)d_in[4];
    const float* fc_c_w   = (const float*)d_in[5];
    const float* fc_c_b   = (const float*)d_in[6];
    const float* conv_w   = (const float*)d_in[7];
    const float* conv_b   = (const float*)d_in[8];
    const float* fc1_w    = (const float*)d_in[9];
    const float* fc1_b    = (const float*)d_in[10];
    const float* fc2_w    = (const float*)d_in[11];
    const float* fc2_b    = (const float*)d_in[12];
    float* out = (float*)d_out;

    // Fork: copy (the long pole, no deps) runs on s1 immediately;
    // main stream runs transpose -> compute concurrently with it.
    cudaStream_t s1;
    cudaStreamCreateWithFlags(&s1, cudaStreamNonBlocking);
    cudaEvent_t evFork, evJoin;
    cudaEventCreateWithFlags(&evFork, cudaEventDisableTiming);
    cudaEventCreateWithFlags(&evJoin, cudaEventDisableTiming);

    cudaEventRecord(evFork, 0);
    cudaStreamWaitEvent(s1, evFork, 0);

    queue_copy_kernel<<<NCOPY, NTHREADS, 0, s1>>>(queues, out);

    transpose_weights_kernel<<<(NCONVP + NTHREADS - 1) / NTHREADS, NTHREADS>>>(
        conv_w, fc1_w);
    wave_compute_kernel<<<NCOMP, CTHREADS>>>(
        x, features, queues, fc_h_w, fc_h_b, fc_c_w, fc_c_b,
        conv_b, fc1_b, fc2_w, fc2_b, out);

    cudaEventRecord(evJoin, s1);
    cudaStreamWaitEvent(0, evJoin, 0);

    cudaStreamDestroy(s1);
    cudaEventDestroy(evFork);
    cudaEventDestroy(evJoin);
}

// round 14
// speedup vs baseline: 1.1785x; 1.1599x over previous
#include <cuda_runtime.h>

#define BATCH 1024
#define RC 64
#define NL 24
#define QL 128
#define TB 4                     // batch rows per compute block
#define NCOMP (BATCH / TB)       // 256 compute blocks
#define CTHREADS 512             // 2 independent groups of 256
#define NTHREADS 256
#define NQ ((size_t)NL * BATCH * RC * QL)   // 201326592 queue elements
#define NROWS (NQ / 128)                    // 1572864 rows of 128 floats
#define LSTR ((size_t)BATCH * RC)           // row index stride per layer
#define NCONVP (NL * 32 * 256)              // packed conv float4 count
#define NFC1P  (NL * 16 * 256)              // packed fc1 float4 count

// ---- copy kernel geometry: 4-row groups are contiguous+aligned in dst ----
#define BG 8                                // 4-row groups per copy block
#define CP_ROWS (4 * BG)                    // 32 rows per block
#define CP_SRC_F4 (CP_ROWS * 128 / 4)       // 1024 src float4 per block
#define CP_DST_F  (CP_ROWS * 129)           // 4128 dst floats per block
#define CP_DST_F4 (CP_DST_F / 4)            // 1032 dst float4 per block
#define NCOPY ((int)(NROWS / CP_ROWS))      // 49152 copy blocks

// Packed transposed weights, lane-coalesced for thread==j mapping.
__device__ float4 g_convP[NCONVP];   // [i][p][j] = (w0[2p],w1[2p],w0[2p+1],w1[2p+1])
__device__ float4 g_fc1P[NFC1P];     // [i][q][j] = fc1[rc=4q..4q+3]

__device__ __forceinline__ float sigf(float x) { return 1.0f / (1.0f + __expf(-x)); }

#define GBAR(g) asm volatile("bar.sync %0, %1;" :: "r"((g) + 1), "r"(256) : "memory")

// ---------------------------------------------------------------------------
// WEIGHT TRANSPOSE (packed float4)
// ---------------------------------------------------------------------------
__global__ void __launch_bounds__(NTHREADS)
transpose_weights_kernel(const float* __restrict__ conv_w,
                         const float* __restrict__ fc1_w)
{
    int idx = blockIdx.x * NTHREADS + threadIdx.x;   // ((i*32+p)*256+j)
    if (idx < NCONVP) {
        int j  = idx & 255;
        int pi = idx >> 8;           // i*32 + p
        int p  = pi & 31;
        int i  = pi >> 5;
        g_convP[idx] =
            __ldg((const float4*)(conv_w + (((size_t)i * 256 + j) << 7)) + p);
    }
    if (idx < NFC1P) {
        int j  = idx & 255;
        int qi = idx >> 8;           // i*16 + q
        g_fc1P[idx] =
            __ldg((const float4*)(fc1_w + (size_t)j * (NL * RC)) + qi);
    }
}

// ---------------------------------------------------------------------------
// COPY KERNEL v2: fully-aligned stream copy with smem hole insertion.
// Block handles 32 consecutive rows = 4096 src floats -> 4128 dst floats
// (dst region [blk*4128, +4128) is contiguous & 16B-aligned; the 32 entry
// slots inside it get junk that the compute kernel overwrites afterwards).
// ---------------------------------------------------------------------------
__global__ void __launch_bounds__(NTHREADS)
queue_copy_kernel(const float* __restrict__ queues, float* __restrict__ out)
{
    __shared__ __align__(16) float st[CP_DST_F];
    const int tid = threadIdx.x;
    const size_t blk = blockIdx.x;

    // Phase 1: aligned contiguous loads; scatter into smem inserting a hole
    // after every 128 floats (e' = e + e/128).
    const float4* __restrict__ s4 = (const float4*)queues + blk * CP_SRC_F4;
    #pragma unroll
    for (int k = 0; k < CP_SRC_F4 / NTHREADS; k++) {      // 4 iterations
        int e4 = k * NTHREADS + tid;
        float4 v = __ldcs(&s4[e4]);
        int e  = e4 * 4;
        int ep = e + (e >> 7);
        st[ep]     = v.x;
        st[ep + 1] = v.y;
        st[ep + 2] = v.z;
        st[ep + 3] = v.w;
    }
    if (tid < CP_ROWS) st[tid * 129 + 128] = 0.0f;        // junk in holes
    __syncthreads();

    // Phase 2: aligned contiguous STG.128 of the whole staged region.
    float4* __restrict__ d4 = (float4*)(out + BATCH) + blk * CP_DST_F4;
    #pragma unroll
    for (int k = 0; k < (CP_DST_F4 + NTHREADS - 1) / NTHREADS; k++) {
        int e4 = k * NTHREADS + tid;
        if (e4 < CP_DST_F4)
            __stcs(&d4[e4], *(const float4*)&st[e4 * 4]);
    }
}

// ---------------------------------------------------------------------------
// COMPUTE KERNEL: 512 threads, TB=4 rows, two INDEPENDENT 256-thread groups
// (group g owns rows {2g, 2g+1}); per-layer sync is a group-local named
// barrier, decoupling the groups. fc1 of layer i-1 fused into layer i's
// conv loop; packed float4 weights.
// ---------------------------------------------------------------------------
__global__ void __launch_bounds__(CTHREADS, 2)
wave_compute_kernel(const float* __restrict__ x,
                    const float* __restrict__ features,
                    const float* __restrict__ queues,
                    const float* __restrict__ fc_h_w,
                    const float* __restrict__ fc_h_b,
                    const float* __restrict__ fc_c_w,
                    const float* __restrict__ fc_c_b,
                    const float* __restrict__ conv_b,
                    const float* __restrict__ fc1_b,
                    const float* __restrict__ fc2_w,
                    const float* __restrict__ fc2_b,
                    float* __restrict__ out)
{
    __shared__ __align__(16) float s_h[TB][RC];
    __shared__ __align__(16) float s_c[TB][RC];
    __shared__ __align__(16) float s_pv[NL][TB][RC];   // 24 KB prefetched slices
    __shared__ float s_co[TB][4 * RC];

    const int tid = threadIdx.x;
    const int b0  = blockIdx.x * TB;
    const int g   = tid >> 8;          // group 0/1: owns rows t0, t0+1
    const int lid = tid & 255;         // id within group
    const int j   = lid;               // output channel
    const int t0  = g * 2;

    // ---- prefetch ALL 24 layers' dilated queue values into shared ----
    for (int idx = tid; idx < NL * TB * RC; idx += CTHREADS) {
        int i = idx >> 8;              // / (TB*RC)
        int t = (idx >> 6) & 3;
        int r = idx & 63;
        s_pv[i][t][r] = __ldg(queues
            + (((size_t)(b0 + t) * RC + r) + (size_t)i * LSTR) * QL
            + QL - (1 << (i & 7)));
    }

    // ---- initial h, c (each group inits its own 2 rows; 128 threads) ----
    float* __restrict__ outq = out + BATCH;
    if (lid < 128) {
        int t = t0 + (lid >> 6), r = lid & 63;
        int b = b0 + t;
        const float* wh = fc_h_w + r * 33;
        const float* wc = fc_c_w + r * 33;
        float ah = fc_h_b[r], ac = fc_c_b[r];
        float xv = x[b];
        ah += xv * wh[0];
        ac += xv * wc[0];
        const float* fb = features + b * 32;
        #pragma unroll
        for (int k = 0; k < 32; k++) {
            float f = fb[k];
            ah += f * wh[1 + k];
            ac += f * wc[1 + k];
        }
        float h0 = tanhf(ah);
        s_h[t][r] = h0;
        s_c[t][r] = tanhf(ac);
        outq[((size_t)b * RC + r) * 129 + QL] = h0;    // entry for layer 0
    }

    float yacc0 = fc1_b[j], yacc1 = yacc0;
    __syncthreads();                   // s_pv + init visible to all

    const float4* __restrict__ wcv = g_convP + j;   // + (i*32+p)*256
    const float4* __restrict__ wf1 = g_fc1P  + j;   // + (i*16+q)*256

    for (int i = 0; i < NL; i++) {
        // ---- conv layer i (+ fused fc1 of layer i-1, same s_h reads) ----
        float acc0a, acc0b, acc1a, acc1b;
        acc0a = acc1a = __ldg(conv_b + i * 256 + j);
        acc0b = acc1b = 0.0f;
        const float4* wci = wcv + (size_t)i * (32 * 256);
        const float4* f1p = wf1 + (size_t)(i - 1) * (16 * 256);
        const bool addf = (i > 0);
        #pragma unroll 4
        for (int rc = 0; rc < RC; rc += 4) {
            float4 wA = __ldg(&wci[((rc >> 1)    ) << 8]);  // rc, rc+1
            float4 wB = __ldg(&wci[((rc >> 1) + 1) << 8]);  // rc+2, rc+3
            float4 fA = make_float4(0.f, 0.f, 0.f, 0.f);
            if (addf) fA = __ldg(&f1p[(rc >> 2) << 8]);
            {
                float4 p  = *(const float4*)&s_pv[i][t0][rc];
                float4 hh = *(const float4*)&s_h[t0][rc];
                acc0a += p.x * wA.x + hh.x * wA.y;
                acc0b += p.y * wA.z + hh.y * wA.w;
                acc0a += p.z * wB.x + hh.z * wB.y;
                acc0b += p.w * wB.z + hh.w * wB.w;
                yacc0 += hh.x * fA.x + hh.y * fA.y + hh.z * fA.z + hh.w * fA.w;
            }
            {
                float4 p  = *(const float4*)&s_pv[i][t0 + 1][rc];
                float4 hh = *(const float4*)&s_h[t0 + 1][rc];
                acc1a += p.x * wA.x + hh.x * wA.y;
                acc1b += p.y * wA.z + hh.y * wA.w;
                acc1a += p.z * wB.x + hh.z * wB.y;
                acc1b += p.w * wB.z + hh.w * wB.w;
                yacc1 += hh.x * fA.x + hh.y * fA.y + hh.z * fA.z + hh.w * fA.w;
            }
        }
        s_co[t0][j]     = acc0a + acc0b;
        s_co[t0 + 1][j] = acc1a + acc1b;
        GBAR(g);                       // group-local: s_co rows ready

        // ---- gate update: lower 128 threads of this group, own rows ----
        if (lid < 128) {
            int t = t0 + (lid >> 6), r = lid & 63;
            float ig = s_co[t][r];
            float cf = s_co[t][RC + r];
            float cg = s_co[t][2 * RC + r];
            float eg = s_co[t][3 * RC + r];
            float c = sigf(ig) * s_c[t][r] + tanhf(cf) * sigf(cg);
            float h = sigf(eg) * tanhf(c);
            s_c[t][r] = c;
            s_h[t][r] = h;
            if (i + 1 < NL)            // entry_h for layer i+1
                outq[(((size_t)(b0 + t) * RC + r)
                      + (size_t)(i + 1) * LSTR) * 129 + QL] = h;
        }
        GBAR(g);                       // group-local: s_h rows updated
    }

    // ---- trailing fc1 for layer 23's skip-h ----
    {
        const float4* f1p = wf1 + (size_t)(NL - 1) * (16 * 256);
        #pragma unroll 4
        for (int rc = 0; rc < RC; rc += 4) {
            float4 fA = __ldg(&f1p[(rc >> 2) << 8]);
            {
                float4 hh = *(const float4*)&s_h[t0][rc];
                yacc0 += hh.x * fA.x + hh.y * fA.y + hh.z * fA.z + hh.w * fA.w;
            }
            {
                float4 hh = *(const float4*)&s_h[t0 + 1][rc];
                yacc1 += hh.x * fA.x + hh.y * fA.y + hh.z * fA.z + hh.w * fA.w;
            }
        }
    }

    // ---- fc2: h_hat[b] = relu(y) @ fc2_w^T + fc2_b ----
    {
        float fw = fc2_w[j];
        s_co[t0][j]     = fmaxf(yacc0, 0.0f) * fw;
        s_co[t0 + 1][j] = fmaxf(yacc1, 0.0f) * fw;
    }
    __syncthreads();

    int w = tid >> 5, lane = tid & 31;
    if (w < TB) {                        // warps 0..3 reduce the TB rows
        float s = 0.0f;
        #pragma unroll
        for (int k = 0; k < 8; k++) s += s_co[w][lane + k * 32];
        #pragma unroll
        for (int o = 16; o > 0; o >>= 1) s += __shfl_xor_sync(0xffffffffu, s, o);
        if (lane == 0) out[b0 + w] = s + fc2_b[0];
    }
}

extern "C" void kernel_launch(void* const* d_in, const int* in_sizes, int n_in,
                              void* d_out, int out_size)
{
    const float* x        = (const float*)d_in[0];
    const float* features = (const float*)d_in[1];
    const float* queues   = (const float*)d_in[2];
    const float* fc_h_w   = (const float*)d_in[3];
    const float* fc_h_b   = (const float*)d_in[4];
    const float* fc_c_w   = (const float*)d_in[5];
    const float* fc_c_b   = (const float*)d_in[6];
    const float* conv_w   = (const float*)d_in[7];
    const float* conv_b   = (const float*)d_in[8];
    const float* fc1_w    = (const float*)d_in[9];
    const float* fc1_b    = (const float*)d_in[10];
    const float* fc2_w    = (const float*)d_in[11];
    const float* fc2_b    = (const float*)d_in[12];
    float* out = (float*)d_out;

    // Serial, single stream. COPY MUST PRECEDE COMPUTE: the copy writes junk
    // into the entry slots, which the compute kernel then overwrites.
    queue_copy_kernel<<<NCOPY, NTHREADS>>>(queues, out);

    transpose_weights_kernel<<<(NCONVP + NTHREADS - 1) / NTHREADS, NTHREADS>>>(
        conv_w, fc1_w);

    wave_compute_kernel<<<NCOMP, CTHREADS>>>(
        x, features, queues, fc_h_w, fc_h_b, fc_c_w, fc_c_b,
        conv_b, fc1_b, fc2_w, fc2_b, out);
}

// round 15
// speedup vs baseline: 1.2534x; 1.0636x over previous
#include <cuda_runtime.h>

#define BATCH 1024
#define RC 64
#define NL 24
#define QL 128
#define TB 4                     // batch rows per compute block
#define NCOMP (BATCH / TB)       // 256 compute blocks
#define CTHREADS 512             // 2 independent groups of 256
#define NTHREADS 256
#define NQ ((size_t)NL * BATCH * RC * QL)   // 201326592 queue elements
#define NROWS (NQ / 128)                    // 1572864 rows of 128 floats
#define LSTR ((size_t)BATCH * RC)           // row index stride per layer
#define NCONVP (NL * 32 * 256)              // packed conv float4 count
#define NFC1P  (NL * 16 * 256)              // packed fc1 float4 count

// ---- copy kernel geometry: 4-row groups are contiguous+aligned in dst ----
#define BG 8                                // 4-row groups per copy block
#define CP_ROWS (4 * BG)                    // 32 rows per block
#define CP_SRC_F4 (CP_ROWS * 128 / 4)       // 1024 src float4 per block
#define CP_DST_F  (CP_ROWS * 129)           // 4128 dst floats per block
#define CP_DST_F4 (CP_DST_F / 4)            // 1032 dst float4 per block
#define NCOPY ((int)(NROWS / CP_ROWS))      // 49152 copy blocks

typedef unsigned long long u64;

// Packed transposed weights, lane-coalesced for thread==j mapping.
// g_convP[(i*32+p)*256+j] = (w0[2p], w0[2p+1], w1[2p], w1[2p+1])
//   -> as ulonglong2: .x = f32x2 pair of w0, .y = f32x2 pair of w1
// g_fc1P [(i*16+q)*256+j] = fc1[rc=4q..4q+3] (two natural f32x2 pairs)
__device__ float4 g_convP[NCONVP];
__device__ float4 g_fc1P[NFC1P];

__device__ __forceinline__ float sigf(float x) { return 1.0f / (1.0f + __expf(-x)); }

__device__ __forceinline__ void fma2(u64& d, u64 a, u64 b) {
    asm("fma.rn.f32x2 %0, %1, %2, %3;" : "=l"(d) : "l"(a), "l"(b), "l"(d));
}
__device__ __forceinline__ u64 pk(float lo, float hi) {
    u64 r; asm("mov.b64 %0, {%1, %2};" : "=l"(r) : "f"(lo), "f"(hi)); return r;
}
__device__ __forceinline__ float hadd2(u64 v) {
    float lo, hi;
    asm("mov.b64 {%0, %1}, %2;" : "=f"(lo), "=f"(hi) : "l"(v));
    return lo + hi;
}

#define GBAR(g) asm volatile("bar.sync %0, %1;" :: "r"((g) + 1), "r"(256) : "memory")

// ---------------------------------------------------------------------------
// WEIGHT TRANSPOSE (packed float4, rc-pairwise reorder for f32x2)
// ---------------------------------------------------------------------------
__global__ void __launch_bounds__(NTHREADS)
transpose_weights_kernel(const float* __restrict__ conv_w,
                         const float* __restrict__ fc1_w)
{
    int idx = blockIdx.x * NTHREADS + threadIdx.x;   // ((i*32+p)*256+j)
    if (idx < NCONVP) {
        int j  = idx & 255;
        int pi = idx >> 8;           // i*32 + p
        int p  = pi & 31;
        int i  = pi >> 5;
        float4 v =
            __ldg((const float4*)(conv_w + (((size_t)i * 256 + j) << 7)) + p);
        // src float4 #p = (w0[2p], w1[2p], w0[2p+1], w1[2p+1])
        g_convP[idx] = make_float4(v.x, v.z, v.y, v.w);
    }
    if (idx < NFC1P) {
        int j  = idx & 255;
        int qi = idx >> 8;           // i*16 + q
        g_fc1P[idx] =
            __ldg((const float4*)(fc1_w + (size_t)j * (NL * RC)) + qi);
    }
}

// ---------------------------------------------------------------------------
// COPY KERNEL v2: fully-aligned stream copy with smem hole insertion.
// (Proven: 228us standalone, 86.5% DRAM.)
// ---------------------------------------------------------------------------
__global__ void __launch_bounds__(NTHREADS)
queue_copy_kernel(const float* __restrict__ queues, float* __restrict__ out)
{
    __shared__ __align__(16) float st[CP_DST_F];
    const int tid = threadIdx.x;
    const size_t blk = blockIdx.x;

    const float4* __restrict__ s4 = (const float4*)queues + blk * CP_SRC_F4;
    #pragma unroll
    for (int k = 0; k < CP_SRC_F4 / NTHREADS; k++) {      // 4 iterations
        int e4 = k * NTHREADS + tid;
        float4 v = __ldcs(&s4[e4]);
        int e  = e4 * 4;
        int ep = e + (e >> 7);
        st[ep]     = v.x;
        st[ep + 1] = v.y;
        st[ep + 2] = v.z;
        st[ep + 3] = v.w;
    }
    if (tid < CP_ROWS) st[tid * 129 + 128] = 0.0f;        // junk in holes
    __syncthreads();

    float4* __restrict__ d4 = (float4*)(out + BATCH) + blk * CP_DST_F4;
    #pragma unroll
    for (int k = 0; k < (CP_DST_F4 + NTHREADS - 1) / NTHREADS; k++) {
        int e4 = k * NTHREADS + tid;
        if (e4 < CP_DST_F4)
            __stcs(&d4[e4], *(const float4*)&st[e4 * 4]);
    }
}

// ---------------------------------------------------------------------------
// COMPUTE KERNEL: 512 threads, TB=4 rows, two independent 256-thread groups
// (group g owns rows {2g, 2g+1}); per-layer group-local barriers. fc1 of
// layer i-1 fused into layer i's conv loop. All dot products in packed
// fma.rn.f32x2 (rc-pairwise): 12 FMA2 per 4-rc instead of 24 FFMA.
// ---------------------------------------------------------------------------
__global__ void __launch_bounds__(CTHREADS, 2)
wave_compute_kernel(const float* __restrict__ x,
                    const float* __restrict__ features,
                    const float* __restrict__ queues,
                    const float* __restrict__ fc_h_w,
                    const float* __restrict__ fc_h_b,
                    const float* __restrict__ fc_c_w,
                    const float* __restrict__ fc_c_b,
                    const float* __restrict__ conv_b,
                    const float* __restrict__ fc1_b,
                    const float* __restrict__ fc2_w,
                    const float* __restrict__ fc2_b,
                    float* __restrict__ out)
{
    __shared__ __align__(16) float s_h[TB][RC];
    __shared__ __align__(16) float s_c[TB][RC];
    __shared__ __align__(16) float s_pv[NL][TB][RC];   // 24 KB prefetched slices
    __shared__ float s_co[TB][4 * RC];

    const int tid = threadIdx.x;
    const int b0  = blockIdx.x * TB;
    const int g   = tid >> 8;          // group 0/1: owns rows t0, t0+1
    const int lid = tid & 255;         // id within group
    const int j   = lid;               // output channel
    const int t0  = g * 2;

    // ---- prefetch ALL 24 layers' dilated queue values into shared ----
    for (int idx = tid; idx < NL * TB * RC; idx += CTHREADS) {
        int i = idx >> 8;              // / (TB*RC)
        int t = (idx >> 6) & 3;
        int r = idx & 63;
        s_pv[i][t][r] = __ldg(queues
            + (((size_t)(b0 + t) * RC + r) + (size_t)i * LSTR) * QL
            + QL - (1 << (i & 7)));
    }

    // ---- initial h, c (each group inits its own 2 rows; 128 threads) ----
    float* __restrict__ outq = out + BATCH;
    if (lid < 128) {
        int t = t0 + (lid >> 6), r = lid & 63;
        int b = b0 + t;
        const float* wh = fc_h_w + r * 33;
        const float* wc = fc_c_w + r * 33;
        float ah = fc_h_b[r], ac = fc_c_b[r];
        float xv = x[b];
        ah += xv * wh[0];
        ac += xv * wc[0];
        const float* fb = features + b * 32;
        #pragma unroll
        for (int k = 0; k < 32; k++) {
            float f = fb[k];
            ah += f * wh[1 + k];
            ac += f * wc[1 + k];
        }
        float h0 = tanhf(ah);
        s_h[t][r] = h0;
        s_c[t][r] = tanhf(ac);
        outq[((size_t)b * RC + r) * 129 + QL] = h0;    // entry for layer 0
    }

    u64 y0 = pk(fc1_b[j], 0.0f), y1 = y0;
    __syncthreads();                   // s_pv + init visible to all

    const ulonglong2* __restrict__ wcv = (const ulonglong2*)g_convP + j;
    const ulonglong2* __restrict__ wf1 = (const ulonglong2*)g_fc1P  + j;

    for (int i = 0; i < NL; i++) {
        // ---- conv layer i (+ fused fc1 of layer i-1, same s_h reads) ----
        u64 acc0 = pk(__ldg(conv_b + i * 256 + j), 0.0f);
        u64 acc1 = acc0;
        const ulonglong2* wci = wcv + (size_t)i * (32 * 256);
        const ulonglong2* f1p = wf1 + (size_t)(i - 1) * (16 * 256);
        const bool addf = (i > 0);
        #pragma unroll 4
        for (int rc = 0; rc < RC; rc += 4) {
            // wA: rc,rc+1  (.x = w0 pair, .y = w1 pair); wB: rc+2,rc+3
            ulonglong2 wA = __ldg(&wci[((rc >> 1)    ) << 8]);
            ulonglong2 wB = __ldg(&wci[((rc >> 1) + 1) << 8]);
            ulonglong2 fA = make_ulonglong2(0ull, 0ull);
            if (addf) fA = __ldg(&f1p[(rc >> 2) << 8]);
            {
                ulonglong2 P = *(const ulonglong2*)&s_pv[i][t0][rc];
                ulonglong2 H = *(const ulonglong2*)&s_h[t0][rc];
                fma2(acc0, P.x, wA.x);
                fma2(acc0, H.x, wA.y);
                fma2(acc0, P.y, wB.x);
                fma2(acc0, H.y, wB.y);
                fma2(y0,   H.x, fA.x);
                fma2(y0,   H.y, fA.y);
            }
            {
                ulonglong2 P = *(const ulonglong2*)&s_pv[i][t0 + 1][rc];
                ulonglong2 H = *(const ulonglong2*)&s_h[t0 + 1][rc];
                fma2(acc1, P.x, wA.x);
                fma2(acc1, H.x, wA.y);
                fma2(acc1, P.y, wB.x);
                fma2(acc1, H.y, wB.y);
                fma2(y1,   H.x, fA.x);
                fma2(y1,   H.y, fA.y);
            }
        }
        s_co[t0][j]     = hadd2(acc0);
        s_co[t0 + 1][j] = hadd2(acc1);
        GBAR(g);                       // group-local: s_co rows ready

        // ---- gate update: lower 128 threads of this group, own rows ----
        if (lid < 128) {
            int t = t0 + (lid >> 6), r = lid & 63;
            float ig = s_co[t][r];
            float cf = s_co[t][RC + r];
            float cg = s_co[t][2 * RC + r];
            float eg = s_co[t][3 * RC + r];
            float c = sigf(ig) * s_c[t][r] + tanhf(cf) * sigf(cg);
            float h = sigf(eg) * tanhf(c);
            s_c[t][r] = c;
            s_h[t][r] = h;
            if (i + 1 < NL)            // entry_h for layer i+1
                outq[(((size_t)(b0 + t) * RC + r)
                      + (size_t)(i + 1) * LSTR) * 129 + QL] = h;
        }
        GBAR(g);                       // group-local: s_h rows updated
    }

    // ---- trailing fc1 for layer 23's skip-h ----
    {
        const ulonglong2* f1p = wf1 + (size_t)(NL - 1) * (16 * 256);
        #pragma unroll 4
        for (int rc = 0; rc < RC; rc += 4) {
            ulonglong2 fA = __ldg(&f1p[(rc >> 2) << 8]);
            {
                ulonglong2 H = *(const ulonglong2*)&s_h[t0][rc];
                fma2(y0, H.x, fA.x);
                fma2(y0, H.y, fA.y);
            }
            {
                ulonglong2 H = *(const ulonglong2*)&s_h[t0 + 1][rc];
                fma2(y1, H.x, fA.x);
                fma2(y1, H.y, fA.y);
            }
        }
    }

    // ---- fc2: h_hat[b] = relu(y) @ fc2_w^T + fc2_b ----
    {
        float fw = fc2_w[j];
        s_co[t0][j]     = fmaxf(hadd2(y0), 0.0f) * fw;
        s_co[t0 + 1][j] = fmaxf(hadd2(y1), 0.0f) * fw;
    }
    __syncthreads();

    int w = tid >> 5, lane = tid & 31;
    if (w < TB) {                        // warps 0..3 reduce the TB rows
        float s = 0.0f;
        #pragma unroll
        for (int k = 0; k < 8; k++) s += s_co[w][lane + k * 32];
        #pragma unroll
        for (int o = 16; o > 0; o >>= 1) s += __shfl_xor_sync(0xffffffffu, s, o);
        if (lane == 0) out[b0 + w] = s + fc2_b[0];
    }
}

extern "C" void kernel_launch(void* const* d_in, const int* in_sizes, int n_in,
                              void* d_out, int out_size)
{
    const float* x        = (const float*)d_in[0];
    const float* features = (const float*)d_in[1];
    const float* queues   = (const float*)d_in[2];
    const float* fc_h_w   = (const float*)d_in[3];
    const float* fc_h_b   = (const float*)d_in[4];
    const float* fc_c_w   = (const float*)d_in[5];
    const float* fc_c_b   = (const float*)d_in[6];
    const float* conv_w   = (const float*)d_in[7];
    const float* conv_b   = (const float*)d_in[8];
    const float* fc1_w    = (const float*)d_in[9];
    const float* fc1_b    = (const float*)d_in[10];
    const float* fc2_w    = (const float*)d_in[11];
    const float* fc2_b    = (const float*)d_in[12];
    float* out = (float*)d_out;

    // Serial, single stream. COPY MUST PRECEDE COMPUTE: the copy writes junk
    // into the entry slots, which the compute kernel then overwrites.
    queue_copy_kernel<<<NCOPY, NTHREADS>>>(queues, out);

    transpose_weights_kernel<<<(NCONVP + NTHREADS - 1) / NTHREADS, NTHREADS>>>(
        conv_w, fc1_w);

    wave_compute_kernel<<<NCOMP, CTHREADS>>>(
        x, features, queues, fc_h_w, fc_h_b, fc_c_w, fc_c_b,
        conv_b, fc1_b, fc2_w, fc2_b, out);
}